// round 13
// baseline (speedup 1.0000x reference)
#include <cuda_runtime.h>
#include <math.h>

// Problem constants
#define Bc 4
#define Sc 512
#define Hc 1024
#define Ec 8
#define Ic 2048
#define BSc (Bc*Sc)     // 2048 rows of x
#define EIc (Ec*Ic)     // 16384 fused K for final GEMM

// ------------------- scratch (device globals; no runtime allocation) -------
__device__ float  g_keys[BSc*Hc];               // [B*S, H]
__device__ float  g_state[(long)Ec*BSc*Hc];     // [E, B*S, H]
__device__ float  g_q[(long)Ec*BSc*Hc];         // [E, B*S, H]
__device__ float  g_logits[(long)Ec*Bc*Sc*Sc];  // [E*B, S, S]
__device__ float  g_T[(long)BSc*EIc];           // [B*S, E*I]  (g*u*coef)
__device__ double g_wvsum[Hc];
__device__ double g_vsum[BSc];
__device__ float  g_qbias[Ec*Hc];               // bs@Wq + bq (null-token q)
__device__ double g_lnull[Ec*Bc*Sc];
__device__ double g_attnreal[Ec*Bc*Sc];
__device__ double g_attnnull[Ec*Bc];
__device__ float  g_coef[Ec*BSc];

// ------------------- f32x2 helpers ------------------------------------------
__device__ __forceinline__ unsigned long long pack_dup(float a) {
    unsigned long long r;
    asm("mov.b64 %0, {%1, %1};" : "=l"(r) : "f"(a));
    return r;
}
__device__ __forceinline__ void ffma2(unsigned long long& d,
                                      unsigned long long a, unsigned long long b) {
    asm("fma.rn.f32x2 %0, %1, %2, %0;" : "+l"(d) : "l"(a), "l"(b));
}
__device__ __forceinline__ float2 unpack2(unsigned long long v) {
    float lo, hi;
    asm("mov.b64 {%0, %1}, %2;" : "=f"(lo), "=f"(hi) : "l"(v));
    return make_float2(lo, hi);
}

// ------------------- tiled SGEMM (f32x2, double-buffered) -------------------
// 128x128 tile, BK=16, 256 threads, 8x8 per-thread register tile.
constexpr int BM = 128, BN = 128, BK = 16, TM = 8, TN = 8;

enum { EPI_NONE = 0, EPI_BIAS = 1, EPI_GU = 2 };

template<int EPI, bool TB>
__global__ __launch_bounds__(256, 2)
void gemm_k(const float* __restrict__ Ag, long sA,
            const float* __restrict__ Bg, long sB, int bMod,
            float* __restrict__ Cg, long sC,
            int M, int N, int K, int lda, int ldb, int ldc,
            const float* __restrict__ bias, long sBias,
            const float* __restrict__ coef, long sCoef)
{
    const int z = blockIdx.z;
    const float* A = Ag + (long)z * sA;
    const float* B = Bg + (long)(bMod ? (z % bMod) : z) * sB;
    float* C = Cg + (long)z * sC;

    __shared__ __align__(16) float As[2][BK][BM + 4];
    __shared__ __align__(16) float Bs[2][BK][BN + 4];

    const int tid  = threadIdx.x;
    const int tcol = tid & 15;     // 0..15
    const int trow = tid >> 4;     // 0..15
    const int row0 = blockIdx.y * BM;
    const int col0 = blockIdx.x * BN;

    // A-staging coords: idx = tid + it*256 -> r = idx>>2, c4 = (idx&3)*4
    const int arow  = tid >> 2;
    const int ac4   = (tid & 3) * 4;
    // B-staging coords (non-TB): r = idx>>5, c4 = (idx&31)*4
    const int brow  = tid >> 5;
    const int bc4   = (tid & 31) * 4;

    float4 ra[2], rb[2];

    auto loadA = [&](int k0) {
        ra[0] = *reinterpret_cast<const float4*>(&A[(long)(row0 + arow      ) * lda + k0 + ac4]);
        ra[1] = *reinterpret_cast<const float4*>(&A[(long)(row0 + arow + 64 ) * lda + k0 + ac4]);
    };
    auto storeA = [&](int p) {
        #pragma unroll
        for (int it = 0; it < 2; it++) {
            int r = arow + it * 64;
            As[p][ac4 + 0][r] = (it ? ra[1].x : ra[0].x);
            As[p][ac4 + 1][r] = (it ? ra[1].y : ra[0].y);
            As[p][ac4 + 2][r] = (it ? ra[1].z : ra[0].z);
            As[p][ac4 + 3][r] = (it ? ra[1].w : ra[0].w);
        }
    };
    auto loadB = [&](int k0) {
        if (TB) {
            rb[0] = *reinterpret_cast<const float4*>(&B[(long)(col0 + arow      ) * ldb + k0 + ac4]);
            rb[1] = *reinterpret_cast<const float4*>(&B[(long)(col0 + arow + 64 ) * ldb + k0 + ac4]);
        } else {
            rb[0] = *reinterpret_cast<const float4*>(&B[(long)(k0 + brow     ) * ldb + col0 + bc4]);
            rb[1] = *reinterpret_cast<const float4*>(&B[(long)(k0 + brow + 8 ) * ldb + col0 + bc4]);
        }
    };
    auto storeB = [&](int p) {
        if (TB) {
            #pragma unroll
            for (int it = 0; it < 2; it++) {
                int r = arow + it * 64;
                Bs[p][ac4 + 0][r] = (it ? rb[1].x : rb[0].x);
                Bs[p][ac4 + 1][r] = (it ? rb[1].y : rb[0].y);
                Bs[p][ac4 + 2][r] = (it ? rb[1].z : rb[0].z);
                Bs[p][ac4 + 3][r] = (it ? rb[1].w : rb[0].w);
            }
        } else {
            *reinterpret_cast<float4*>(&Bs[p][brow    ][bc4]) = rb[0];
            *reinterpret_cast<float4*>(&Bs[p][brow + 8][bc4]) = rb[1];
        }
    };

    unsigned long long acc[TM][TN/2];
    #pragma unroll
    for (int i = 0; i < TM; i++)
        #pragma unroll
        for (int j = 0; j < TN/2; j++) acc[i][j] = 0ull;   // (0.0f, 0.0f)

    const int nt = K / BK;
    loadA(0); loadB(0);
    storeA(0); storeB(0);
    __syncthreads();

    for (int t = 0; t < nt; t++) {
        const int p = t & 1;
        if (t + 1 < nt) { loadA((t + 1) * BK); loadB((t + 1) * BK); }

        #pragma unroll
        for (int kk = 0; kk < BK; kk++) {
            float4 m0 = *reinterpret_cast<const float4*>(&As[p][kk][trow * TM]);
            float4 m1 = *reinterpret_cast<const float4*>(&As[p][kk][trow * TM + 4]);
            unsigned long long n2[4];
            #pragma unroll
            for (int j = 0; j < 4; j++)
                n2[j] = *reinterpret_cast<const unsigned long long*>(
                            &Bs[p][kk][tcol * TN + 2 * j]);
            float mv[8] = {m0.x, m0.y, m0.z, m0.w, m1.x, m1.y, m1.z, m1.w};
            #pragma unroll
            for (int i = 0; i < 8; i++) {
                unsigned long long am = pack_dup(mv[i]);
                #pragma unroll
                for (int j = 0; j < 4; j++) ffma2(acc[i][j], am, n2[j]);
            }
        }

        if (t + 1 < nt) { storeA(p ^ 1); storeB(p ^ 1); }
        __syncthreads();
    }

    // ---- epilogue (float2 granularity; per-element math identical to before)
    #pragma unroll
    for (int i = 0; i < TM; i++) {
        int m = row0 + trow * TM + i;
        #pragma unroll
        for (int j = 0; j < TN/2; j++) {
            int n = col0 + tcol * TN + 2 * j;
            long off = (long)m * ldc + n;
            float2 v = unpack2(acc[i][j]);
            if (EPI == EPI_BIAS) {
                v.x += bias[(long)z * sBias + n];
                v.y += bias[(long)z * sBias + n + 1];
            }
            if (EPI == EPI_GU) {
                float2 g = *reinterpret_cast<const float2*>(&C[off]);
                float cf = coef[(long)z * sCoef + m];
                float sx = g.x / (1.0f + expf(-g.x));
                float sy = g.y / (1.0f + expf(-g.y));
                v.x = sx * v.x * cf;
                v.y = sy * v.y * cf;
            }
            *reinterpret_cast<float2*>(&C[off]) = v;
        }
    }
}

// ------------------- small kernels (fp64 reductions) ------------------------
__device__ __forceinline__ double blk_reduce_sum(double s, double* sh)
{
    #pragma unroll
    for (int o = 16; o; o >>= 1) s += __shfl_xor_sync(~0u, s, o);
    if ((threadIdx.x & 31) == 0) sh[threadIdx.x >> 5] = s;
    __syncthreads();
    double t = 0.0;
    int nw = blockDim.x >> 5;
    if (threadIdx.x == 0)
        for (int i = 0; i < nw; i++) t += sh[i];
    return t;   // valid in thread 0 only
}

__global__ void k_rowsum(const float* __restrict__ W, double* __restrict__ out, int ncols)
{
    __shared__ double sh[8];
    int r = blockIdx.x;
    double s = 0.0;
    for (int c = threadIdx.x; c < ncols; c += blockDim.x) s += (double)W[(long)r * ncols + c];
    double t = blk_reduce_sum(s, sh);
    if (threadIdx.x == 0) out[r] = t;
}

__global__ void k_vsum(const float* __restrict__ x, const double* __restrict__ wvsum,
                       double* __restrict__ vsum)
{
    __shared__ double sh[8];
    int r = blockIdx.x;
    double s = 0.0;
    for (int h = threadIdx.x; h < Hc; h += blockDim.x)
        s += (double)x[(long)r * Hc + h] * wvsum[h];
    double t = blk_reduce_sum(s, sh);
    if (threadIdx.x == 0) vsum[r] = t;
}

__global__ void k_qbias(const float* __restrict__ bs, const float* __restrict__ Wq,
                        const float* __restrict__ bq, float* __restrict__ qbias)
{
    int e = blockIdx.y;
    int d = blockIdx.x * blockDim.x + threadIdx.x;
    const float* Wqe = Wq + (long)e * Hc * Hc;
    double s = (double)bq[e * Hc + d];
    for (int h = 0; h < Hc; h++)
        s += (double)bs[e * Hc + h] * (double)Wqe[(long)h * Hc + d];
    qbias[e * Hc + d] = (float)s;
}

__global__ void k_lnull(const float* __restrict__ qbias, const float* __restrict__ keys,
                        double* __restrict__ lnull)
{
    __shared__ double sh[8];
    int idx = blockIdx.x;                 // e*B*S + b*S + s
    int e  = idx / (Bc * Sc);
    int bs = idx % (Bc * Sc);             // row in keys
    double s = 0.0;
    for (int h = threadIdx.x; h < Hc; h += blockDim.x)
        s += (double)qbias[e * Hc + h] * (double)keys[(long)bs * Hc + h];
    double t = blk_reduce_sum(s, sh);
    if (threadIdx.x == 0) lnull[idx] = t;
}

// softmax over S real logits + Sc implicit null columns at logit 0;
// simultaneously dot with vsum -> attn value. All reductions fp64.
template<typename TL>
__device__ __forceinline__ void softmax_dot(const TL* __restrict__ L,
                                            const double* __restrict__ vsumRow,
                                            double* __restrict__ outv)
{
    __shared__ double sh[16];
    const double scale = 0.03125;  // 1/sqrt(1024)
    double m = 0.0;                // null columns contribute logit 0
    for (int s = threadIdx.x; s < Sc; s += 256) m = fmax(m, (double)L[s] * scale);
    #pragma unroll
    for (int o = 16; o; o >>= 1) m = fmax(m, __shfl_xor_sync(~0u, m, o));
    if ((threadIdx.x & 31) == 0) sh[threadIdx.x >> 5] = m;
    __syncthreads();
    double mm = sh[0];
    #pragma unroll
    for (int i = 1; i < 8; i++) mm = fmax(mm, sh[i]);
    __syncthreads();
    double num = 0.0, den = 0.0;
    for (int s = threadIdx.x; s < Sc; s += 256) {
        double p = exp((double)L[s] * scale - mm);
        num += p * vsumRow[s];
        den += p;
    }
    #pragma unroll
    for (int o = 16; o; o >>= 1) {
        num += __shfl_xor_sync(~0u, num, o);
        den += __shfl_xor_sync(~0u, den, o);
    }
    if ((threadIdx.x & 31) == 0) {
        sh[threadIdx.x >> 5] = num;
        sh[8 + (threadIdx.x >> 5)] = den;
    }
    __syncthreads();
    if (threadIdx.x == 0) {
        double N = 0.0, D = 0.0;
        #pragma unroll
        for (int i = 0; i < 8; i++) { N += sh[i]; D += sh[8 + i]; }
        D += (double)Sc * exp(-mm);   // null key columns
        *outv = N / D;
    }
}

__global__ __launch_bounds__(256) void k_softmax_real(const float* __restrict__ logits,
        const double* __restrict__ vsum, double* __restrict__ attnreal)
{
    long row = blockIdx.x;                       // (e*B+b)*S + t
    int b = (int)((row / Sc) % Bc);
    softmax_dot(logits + row * Sc, vsum + (long)b * Sc, attnreal + row);
}

__global__ __launch_bounds__(256) void k_softmax_null(const double* __restrict__ lnull,
        const double* __restrict__ vsum, double* __restrict__ attnnull)
{
    int eb = blockIdx.x;                         // e*B + b
    int b = eb % Bc;
    softmax_dot(lnull + (long)eb * Sc, vsum + (long)b * Sc, attnnull + eb);
}

__global__ void k_coef(const double* __restrict__ attnreal, const double* __restrict__ attnnull,
                       float* __restrict__ coef, float* __restrict__ wout)
{
    int idx = blockIdx.x * blockDim.x + threadIdx.x;   // e*BS + b*S + s
    if (idx >= Ec * BSc) return;
    int eb = idx / Sc;                                 // e*B + b
    double r = attnreal[idx];
    double n = attnnull[eb];
    double w = r / (r + n);
    wout[idx] = (float)w;                              // row-major flatten of [E,B,S]
    coef[idx] = (r - n) > 0.0 ? (float)w : 0.0f;
}

// ------------------- launch -------------------------------------------------
extern "C" void kernel_launch(void* const* d_in, const int* in_sizes, int n_in,
                              void* d_out, int out_size)
{
    const float* x  = (const float*)d_in[0];
    const float* Wk = (const float*)d_in[1];
    const float* Wv = (const float*)d_in[2];
    const float* Ws = (const float*)d_in[3];
    const float* bs = (const float*)d_in[4];
    const float* Wq = (const float*)d_in[5];
    const float* bq = (const float*)d_in[6];
    const float* Wg = (const float*)d_in[7];
    const float* Wu = (const float*)d_in[8];
    const float* Wd = (const float*)d_in[9];

    float* out  = (float*)d_out;                // [B*S, H]
    float* wout = out + (long)BSc * Hc;         // [E*B*S] weights

    float *keys, *state, *q, *logits, *T, *qbias, *coef;
    double *wvsum, *vsum, *lnull, *ar, *an;
    cudaGetSymbolAddress((void**)&keys,   g_keys);
    cudaGetSymbolAddress((void**)&state,  g_state);
    cudaGetSymbolAddress((void**)&q,      g_q);
    cudaGetSymbolAddress((void**)&logits, g_logits);
    cudaGetSymbolAddress((void**)&T,      g_T);
    cudaGetSymbolAddress((void**)&wvsum,  g_wvsum);
    cudaGetSymbolAddress((void**)&vsum,   g_vsum);
    cudaGetSymbolAddress((void**)&qbias,  g_qbias);
    cudaGetSymbolAddress((void**)&lnull,  g_lnull);
    cudaGetSymbolAddress((void**)&ar,     g_attnreal);
    cudaGetSymbolAddress((void**)&an,     g_attnnull);
    cudaGetSymbolAddress((void**)&coef,   g_coef);

    // 1) rowsum(Wv) and vsum = x @ rowsum(Wv)   (fp64)
    k_rowsum<<<Hc, 256>>>(Wv, wvsum, Hc);
    k_vsum<<<BSc, 256>>>(x, wvsum, vsum);

    // 2) keys = x @ Wk     [2048,1024]
    gemm_k<EPI_NONE, false><<<dim3(Hc/BN, BSc/BM, 1), 256>>>(
        x, 0, Wk, 0, 0, keys, 0,
        BSc, Hc, Hc, Hc, Hc, Hc, nullptr, 0, nullptr, 0);

    // 3) state[e] = x @ Ws[e] + bs[e]    (reference association)
    gemm_k<EPI_BIAS, false><<<dim3(Hc/BN, BSc/BM, Ec), 256>>>(
        x, 0, Ws, (long)Hc*Hc, 0, state, (long)BSc*Hc,
        BSc, Hc, Hc, Hc, Hc, Hc, bs, Hc, nullptr, 0);

    // 4) q[e] = state[e] @ Wq[e] + bq[e]
    gemm_k<EPI_BIAS, false><<<dim3(Hc/BN, BSc/BM, Ec), 256>>>(
        state, (long)BSc*Hc, Wq, (long)Hc*Hc, 0, q, (long)BSc*Hc,
        BSc, Hc, Hc, Hc, Hc, Hc, bq, Hc, nullptr, 0);

    // 5) qbias[e] = bs[e] @ Wq[e] + bq[e]   (null-token q; fp64 accum)
    k_qbias<<<dim3(Hc/256, Ec), 256>>>(bs, Wq, bq, qbias);

    // 6) logits[e,b] = q[e,b] @ keys[b]^T    (NT GEMM, 32 batches)
    gemm_k<EPI_NONE, true><<<dim3(Sc/BN, Sc/BM, Ec*Bc), 256>>>(
        q, (long)Sc*Hc, keys, (long)Sc*Hc, Bc, logits, (long)Sc*Sc,
        Sc, Sc, Hc, Hc, Hc, Sc, nullptr, 0, nullptr, 0);

    // 7) lnull[e,b,s] = qbias[e] . keys[b,s]   (fp64)
    k_lnull<<<Ec*Bc*Sc, 128>>>(qbias, keys, lnull);

    // 8) softmax + dot(vsum): real rows and null row   (fp64)
    k_softmax_real<<<Ec*Bc*Sc, 256>>>(logits, vsum, ar);
    k_softmax_null<<<Ec*Bc, 256>>>(lnull, vsum, an);

    // 9) w, mask, coef; write weights output   (fp64 compare)
    k_coef<<<(Ec*BSc + 255)/256, 256>>>(ar, an, coef, wout);

    // 10) T[:, e*I:(e+1)*I] = x @ Wg[e]         (store G)
    gemm_k<EPI_NONE, false><<<dim3(Ic/BN, BSc/BM, Ec), 256>>>(
        x, 0, Wg, (long)Hc*Ic, 0, T, (long)Ic,
        BSc, Ic, Hc, Hc, Ic, EIc, nullptr, 0, nullptr, 0);

    // 11) T = silu(G) * (x @ Wu[e]) * coef[e]
    gemm_k<EPI_GU, false><<<dim3(Ic/BN, BSc/BM, Ec), 256>>>(
        x, 0, Wu, (long)Hc*Ic, 0, T, (long)Ic,
        BSc, Ic, Hc, Hc, Ic, EIc, nullptr, 0, coef, BSc);

    // 12) out = T @ Wd_flat   (M=2048, N=1024, K=16384) — sums all experts
    gemm_k<EPI_NONE, false><<<dim3(Hc/BN, BSc/BM, 1), 256>>>(
        T, 0, Wd, 0, 0, out, 0,
        BSc, Hc, EIc, EIc, Hc, Hc, nullptr, 0, nullptr, 0);
}

// round 14
// speedup vs baseline: 1.0024x; 1.0024x over previous
#include <cuda_runtime.h>
#include <math.h>

// Problem constants
#define Bc 4
#define Sc 512
#define Hc 1024
#define Ec 8
#define Ic 2048
#define BSc (Bc*Sc)     // 2048 rows of x
#define EIc (Ec*Ic)     // 16384 fused K for final GEMM

// ------------------- scratch (device globals; no runtime allocation) -------
__device__ float  g_keys[BSc*Hc];               // [B*S, H]
__device__ float  g_state[(long)Ec*BSc*Hc];     // [E, B*S, H]
__device__ float  g_q[(long)Ec*BSc*Hc];         // [E, B*S, H]
__device__ float  g_logits[(long)Ec*Bc*Sc*Sc];  // [E*B, S, S]
__device__ float  g_T[(long)BSc*EIc];           // [B*S, E*I]  (g*u*coef)
__device__ double g_wvsum[Hc];
__device__ double g_vsum[BSc];
__device__ float  g_qbias[Ec*Hc];               // bs@Wq + bq (null-token q)
__device__ double g_lnull[Ec*Bc*Sc];
__device__ double g_attnreal[Ec*Bc*Sc];
__device__ double g_attnnull[Ec*Bc];
__device__ float  g_coef[Ec*BSc];

// ------------------- f32x2 helpers ------------------------------------------
__device__ __forceinline__ unsigned long long pack_dup(float a) {
    unsigned long long r;
    asm("mov.b64 %0, {%1, %1};" : "=l"(r) : "f"(a));
    return r;
}
__device__ __forceinline__ void ffma2(unsigned long long& d,
                                      unsigned long long a, unsigned long long b) {
    asm("fma.rn.f32x2 %0, %1, %2, %0;" : "+l"(d) : "l"(a), "l"(b));
}
__device__ __forceinline__ float2 unpack2(unsigned long long v) {
    float lo, hi;
    asm("mov.b64 {%0, %1}, %2;" : "=f"(lo), "=f"(hi) : "l"(v));
    return make_float2(lo, hi);
}

// ------------------- tiled SGEMM (f32x2, double-buffered) -------------------
// 128x128 tile, BK=16, 256 threads, 8x8 per-thread register tile.
constexpr int BM = 128, BN = 128, BK = 16, TM = 8, TN = 8;

enum { EPI_NONE = 0, EPI_BIAS = 1, EPI_GU = 2 };

template<int EPI, bool TB>
__global__ __launch_bounds__(256, 2)
void gemm_k(const float* __restrict__ Ag, long sA,
            const float* __restrict__ Bg, long sB, int bMod,
            float* __restrict__ Cg, long sC,
            int M, int N, int K, int lda, int ldb, int ldc,
            const float* __restrict__ bias, long sBias,
            const float* __restrict__ coef, long sCoef)
{
    const int z = blockIdx.z;
    const float* A = Ag + (long)z * sA;
    const float* B = Bg + (long)(bMod ? (z % bMod) : z) * sB;
    float* C = Cg + (long)z * sC;

    __shared__ __align__(16) float As[2][BK][BM + 4];
    __shared__ __align__(16) float Bs[2][BK][BN + 4];

    const int tid  = threadIdx.x;
    const int tcol = tid & 15;     // 0..15
    const int trow = tid >> 4;     // 0..15
    const int row0 = blockIdx.y * BM;
    const int col0 = blockIdx.x * BN;

    // A-staging coords: idx = tid + it*256 -> r = idx>>2, c4 = (idx&3)*4
    const int arow  = tid >> 2;
    const int ac4   = (tid & 3) * 4;
    // B-staging coords (non-TB): r = idx>>5, c4 = (idx&31)*4
    const int brow  = tid >> 5;
    const int bc4   = (tid & 31) * 4;

    float4 ra[2], rb[2];

    auto loadA = [&](int k0) {
        ra[0] = *reinterpret_cast<const float4*>(&A[(long)(row0 + arow      ) * lda + k0 + ac4]);
        ra[1] = *reinterpret_cast<const float4*>(&A[(long)(row0 + arow + 64 ) * lda + k0 + ac4]);
    };
    auto storeA = [&](int p) {
        #pragma unroll
        for (int it = 0; it < 2; it++) {
            int r = arow + it * 64;
            As[p][ac4 + 0][r] = (it ? ra[1].x : ra[0].x);
            As[p][ac4 + 1][r] = (it ? ra[1].y : ra[0].y);
            As[p][ac4 + 2][r] = (it ? ra[1].z : ra[0].z);
            As[p][ac4 + 3][r] = (it ? ra[1].w : ra[0].w);
        }
    };
    auto loadB = [&](int k0) {
        if (TB) {
            rb[0] = *reinterpret_cast<const float4*>(&B[(long)(col0 + arow      ) * ldb + k0 + ac4]);
            rb[1] = *reinterpret_cast<const float4*>(&B[(long)(col0 + arow + 64 ) * ldb + k0 + ac4]);
        } else {
            rb[0] = *reinterpret_cast<const float4*>(&B[(long)(k0 + brow     ) * ldb + col0 + bc4]);
            rb[1] = *reinterpret_cast<const float4*>(&B[(long)(k0 + brow + 8 ) * ldb + col0 + bc4]);
        }
    };
    auto storeB = [&](int p) {
        if (TB) {
            #pragma unroll
            for (int it = 0; it < 2; it++) {
                int r = arow + it * 64;
                Bs[p][ac4 + 0][r] = (it ? rb[1].x : rb[0].x);
                Bs[p][ac4 + 1][r] = (it ? rb[1].y : rb[0].y);
                Bs[p][ac4 + 2][r] = (it ? rb[1].z : rb[0].z);
                Bs[p][ac4 + 3][r] = (it ? rb[1].w : rb[0].w);
            }
        } else {
            *reinterpret_cast<float4*>(&Bs[p][brow    ][bc4]) = rb[0];
            *reinterpret_cast<float4*>(&Bs[p][brow + 8][bc4]) = rb[1];
        }
    };

    unsigned long long acc[TM][TN/2];
    #pragma unroll
    for (int i = 0; i < TM; i++)
        #pragma unroll
        for (int j = 0; j < TN/2; j++) acc[i][j] = 0ull;   // (0.0f, 0.0f)

    const int nt = K / BK;
    loadA(0); loadB(0);
    storeA(0); storeB(0);
    __syncthreads();

    for (int t = 0; t < nt; t++) {
        const int p = t & 1;
        if (t + 1 < nt) { loadA((t + 1) * BK); loadB((t + 1) * BK); }

        #pragma unroll
        for (int kk = 0; kk < BK; kk++) {
            float4 m0 = *reinterpret_cast<const float4*>(&As[p][kk][trow * TM]);
            float4 m1 = *reinterpret_cast<const float4*>(&As[p][kk][trow * TM + 4]);
            unsigned long long n2[4];
            #pragma unroll
            for (int j = 0; j < 4; j++)
                n2[j] = *reinterpret_cast<const unsigned long long*>(
                            &Bs[p][kk][tcol * TN + 2 * j]);
            float mv[8] = {m0.x, m0.y, m0.z, m0.w, m1.x, m1.y, m1.z, m1.w};
            #pragma unroll
            for (int i = 0; i < 8; i++) {
                unsigned long long am = pack_dup(mv[i]);
                #pragma unroll
                for (int j = 0; j < 4; j++) ffma2(acc[i][j], am, n2[j]);
            }
        }

        if (t + 1 < nt) { storeA(p ^ 1); storeB(p ^ 1); }
        __syncthreads();
    }

    // ---- epilogue (float2 granularity; per-element math identical to before)
    #pragma unroll
    for (int i = 0; i < TM; i++) {
        int m = row0 + trow * TM + i;
        #pragma unroll
        for (int j = 0; j < TN/2; j++) {
            int n = col0 + tcol * TN + 2 * j;
            long off = (long)m * ldc + n;
            float2 v = unpack2(acc[i][j]);
            if (EPI == EPI_BIAS) {
                v.x += bias[(long)z * sBias + n];
                v.y += bias[(long)z * sBias + n + 1];
            }
            if (EPI == EPI_GU) {
                float2 g = *reinterpret_cast<const float2*>(&C[off]);
                float cf = coef[(long)z * sCoef + m];
                float sx = g.x / (1.0f + expf(-g.x));
                float sy = g.y / (1.0f + expf(-g.y));
                v.x = sx * v.x * cf;
                v.y = sy * v.y * cf;
            }
            *reinterpret_cast<float2*>(&C[off]) = v;
        }
    }
}

// ------------------- small kernels (fp64 reductions) ------------------------
__device__ __forceinline__ double blk_reduce_sum(double s, double* sh)
{
    #pragma unroll
    for (int o = 16; o; o >>= 1) s += __shfl_xor_sync(~0u, s, o);
    if ((threadIdx.x & 31) == 0) sh[threadIdx.x >> 5] = s;
    __syncthreads();
    double t = 0.0;
    int nw = blockDim.x >> 5;
    if (threadIdx.x == 0)
        for (int i = 0; i < nw; i++) t += sh[i];
    return t;   // valid in thread 0 only
}

__global__ void k_rowsum(const float* __restrict__ W, double* __restrict__ out, int ncols)
{
    __shared__ double sh[8];
    int r = blockIdx.x;
    double s = 0.0;
    for (int c = threadIdx.x; c < ncols; c += blockDim.x) s += (double)W[(long)r * ncols + c];
    double t = blk_reduce_sum(s, sh);
    if (threadIdx.x == 0) out[r] = t;
}

__global__ void k_vsum(const float* __restrict__ x, const double* __restrict__ wvsum,
                       double* __restrict__ vsum)
{
    __shared__ double sh[8];
    int r = blockIdx.x;
    double s = 0.0;
    for (int h = threadIdx.x; h < Hc; h += blockDim.x)
        s += (double)x[(long)r * Hc + h] * wvsum[h];
    double t = blk_reduce_sum(s, sh);
    if (threadIdx.x == 0) vsum[r] = t;
}

__global__ void k_qbias(const float* __restrict__ bs, const float* __restrict__ Wq,
                        const float* __restrict__ bq, float* __restrict__ qbias)
{
    int e = blockIdx.y;
    int d = blockIdx.x * blockDim.x + threadIdx.x;
    const float* Wqe = Wq + (long)e * Hc * Hc;
    double s = (double)bq[e * Hc + d];
    for (int h = 0; h < Hc; h++)
        s += (double)bs[e * Hc + h] * (double)Wqe[(long)h * Hc + d];
    qbias[e * Hc + d] = (float)s;
}

__global__ void k_lnull(const float* __restrict__ qbias, const float* __restrict__ keys,
                        double* __restrict__ lnull)
{
    __shared__ double sh[8];
    int idx = blockIdx.x;                 // e*B*S + b*S + s
    int e  = idx / (Bc * Sc);
    int bs = idx % (Bc * Sc);             // row in keys
    double s = 0.0;
    for (int h = threadIdx.x; h < Hc; h += blockDim.x)
        s += (double)qbias[e * Hc + h] * (double)keys[(long)bs * Hc + h];
    double t = blk_reduce_sum(s, sh);
    if (threadIdx.x == 0) lnull[idx] = t;
}

// softmax over S real logits + Sc implicit null columns at logit 0;
// simultaneously dot with vsum -> attn value. All reductions fp64.
template<typename TL>
__device__ __forceinline__ void softmax_dot(const TL* __restrict__ L,
                                            const double* __restrict__ vsumRow,
                                            double* __restrict__ outv)
{
    __shared__ double sh[16];
    const double scale = 0.03125;  // 1/sqrt(1024)
    double m = 0.0;                // null columns contribute logit 0
    for (int s = threadIdx.x; s < Sc; s += 256) m = fmax(m, (double)L[s] * scale);
    #pragma unroll
    for (int o = 16; o; o >>= 1) m = fmax(m, __shfl_xor_sync(~0u, m, o));
    if ((threadIdx.x & 31) == 0) sh[threadIdx.x >> 5] = m;
    __syncthreads();
    double mm = sh[0];
    #pragma unroll
    for (int i = 1; i < 8; i++) mm = fmax(mm, sh[i]);
    __syncthreads();
    double num = 0.0, den = 0.0;
    for (int s = threadIdx.x; s < Sc; s += 256) {
        double p = exp((double)L[s] * scale - mm);
        num += p * vsumRow[s];
        den += p;
    }
    #pragma unroll
    for (int o = 16; o; o >>= 1) {
        num += __shfl_xor_sync(~0u, num, o);
        den += __shfl_xor_sync(~0u, den, o);
    }
    if ((threadIdx.x & 31) == 0) {
        sh[threadIdx.x >> 5] = num;
        sh[8 + (threadIdx.x >> 5)] = den;
    }
    __syncthreads();
    if (threadIdx.x == 0) {
        double N = 0.0, D = 0.0;
        #pragma unroll
        for (int i = 0; i < 8; i++) { N += sh[i]; D += sh[8 + i]; }
        D += (double)Sc * exp(-mm);   // null key columns
        *outv = N / D;
    }
}

__global__ __launch_bounds__(256) void k_softmax_real(const float* __restrict__ logits,
        const double* __restrict__ vsum, double* __restrict__ attnreal)
{
    long row = blockIdx.x;                       // (e*B+b)*S + t
    int b = (int)((row / Sc) % Bc);
    softmax_dot(logits + row * Sc, vsum + (long)b * Sc, attnreal + row);
}

__global__ __launch_bounds__(256) void k_softmax_null(const double* __restrict__ lnull,
        const double* __restrict__ vsum, double* __restrict__ attnnull)
{
    int eb = blockIdx.x;                         // e*B + b
    int b = eb % Bc;
    softmax_dot(lnull + (long)eb * Sc, vsum + (long)b * Sc, attnnull + eb);
}

__global__ void k_coef(const double* __restrict__ attnreal, const double* __restrict__ attnnull,
                       float* __restrict__ coef, float* __restrict__ wout)
{
    int idx = blockIdx.x * blockDim.x + threadIdx.x;   // e*BS + b*S + s
    if (idx >= Ec * BSc) return;
    int eb = idx / Sc;                                 // e*B + b
    double r = attnreal[idx];
    double n = attnnull[eb];
    double w = r / (r + n);
    wout[idx] = (float)w;                              // row-major flatten of [E,B,S]
    coef[idx] = (r - n) > 0.0 ? (float)w : 0.0f;
}

// ------------------- launch -------------------------------------------------
extern "C" void kernel_launch(void* const* d_in, const int* in_sizes, int n_in,
                              void* d_out, int out_size)
{
    const float* x  = (const float*)d_in[0];
    const float* Wk = (const float*)d_in[1];
    const float* Wv = (const float*)d_in[2];
    const float* Ws = (const float*)d_in[3];
    const float* bs = (const float*)d_in[4];
    const float* Wq = (const float*)d_in[5];
    const float* bq = (const float*)d_in[6];
    const float* Wg = (const float*)d_in[7];
    const float* Wu = (const float*)d_in[8];
    const float* Wd = (const float*)d_in[9];

    float* out  = (float*)d_out;                // [B*S, H]
    float* wout = out + (long)BSc * Hc;         // [E*B*S] weights

    float *keys, *state, *q, *logits, *T, *qbias, *coef;
    double *wvsum, *vsum, *lnull, *ar, *an;
    cudaGetSymbolAddress((void**)&keys,   g_keys);
    cudaGetSymbolAddress((void**)&state,  g_state);
    cudaGetSymbolAddress((void**)&q,      g_q);
    cudaGetSymbolAddress((void**)&logits, g_logits);
    cudaGetSymbolAddress((void**)&T,      g_T);
    cudaGetSymbolAddress((void**)&wvsum,  g_wvsum);
    cudaGetSymbolAddress((void**)&vsum,   g_vsum);
    cudaGetSymbolAddress((void**)&qbias,  g_qbias);
    cudaGetSymbolAddress((void**)&lnull,  g_lnull);
    cudaGetSymbolAddress((void**)&ar,     g_attnreal);
    cudaGetSymbolAddress((void**)&an,     g_attnnull);
    cudaGetSymbolAddress((void**)&coef,   g_coef);

    // 1) rowsum(Wv) and vsum = x @ rowsum(Wv)   (fp64)
    k_rowsum<<<Hc, 256>>>(Wv, wvsum, Hc);
    k_vsum<<<BSc, 256>>>(x, wvsum, vsum);

    // 2) keys = x @ Wk     [2048,1024]
    gemm_k<EPI_NONE, false><<<dim3(Hc/BN, BSc/BM, 1), 256>>>(
        x, 0, Wk, 0, 0, keys, 0,
        BSc, Hc, Hc, Hc, Hc, Hc, nullptr, 0, nullptr, 0);

    // 3) state[e] = x @ Ws[e] + bs[e]    (reference association)
    gemm_k<EPI_BIAS, false><<<dim3(Hc/BN, BSc/BM, Ec), 256>>>(
        x, 0, Ws, (long)Hc*Hc, 0, state, (long)BSc*Hc,
        BSc, Hc, Hc, Hc, Hc, Hc, bs, Hc, nullptr, 0);

    // 4) q[e] = state[e] @ Wq[e] + bq[e]
    gemm_k<EPI_BIAS, false><<<dim3(Hc/BN, BSc/BM, Ec), 256>>>(
        state, (long)BSc*Hc, Wq, (long)Hc*Hc, 0, q, (long)BSc*Hc,
        BSc, Hc, Hc, Hc, Hc, Hc, bq, Hc, nullptr, 0);

    // 5) qbias[e] = bs[e] @ Wq[e] + bq[e]   (null-token q; fp64 accum)
    k_qbias<<<dim3(Hc/256, Ec), 256>>>(bs, Wq, bq, qbias);

    // 6) logits[e,b] = q[e,b] @ keys[b]^T    (NT GEMM, 32 batches)
    gemm_k<EPI_NONE, true><<<dim3(Sc/BN, Sc/BM, Ec*Bc), 256>>>(
        q, (long)Sc*Hc, keys, (long)Sc*Hc, Bc, logits, (long)Sc*Sc,
        Sc, Sc, Hc, Hc, Hc, Sc, nullptr, 0, nullptr, 0);

    // 7) lnull[e,b,s] = qbias[e] . keys[b,s]   (fp64)
    k_lnull<<<Ec*Bc*Sc, 128>>>(qbias, keys, lnull);

    // 8) softmax + dot(vsum): real rows and null row   (fp64)
    k_softmax_real<<<Ec*Bc*Sc, 256>>>(logits, vsum, ar);
    k_softmax_null<<<Ec*Bc, 256>>>(lnull, vsum, an);

    // 9) w, mask, coef; write weights output   (fp64 compare)
    k_coef<<<(Ec*BSc + 255)/256, 256>>>(ar, an, coef, wout);

    // 10) T[:, e*I:(e+1)*I] = x @ Wg[e]         (store G)
    gemm_k<EPI_NONE, false><<<dim3(Ic/BN, BSc/BM, Ec), 256>>>(
        x, 0, Wg, (long)Hc*Ic, 0, T, (long)Ic,
        BSc, Ic, Hc, Hc, Ic, EIc, nullptr, 0, nullptr, 0);

    // 11) T = silu(G) * (x @ Wu[e]) * coef[e]
    gemm_k<EPI_GU, false><<<dim3(Ic/BN, BSc/BM, Ec), 256>>>(
        x, 0, Wu, (long)Hc*Ic, 0, T, (long)Ic,
        BSc, Ic, Hc, Hc, Ic, EIc, nullptr, 0, coef, BSc);

    // 12) out = T @ Wd_flat   (M=2048, N=1024, K=16384) — sums all experts
    gemm_k<EPI_NONE, false><<<dim3(Hc/BN, BSc/BM, 1), 256>>>(
        T, 0, Wd, 0, 0, out, 0,
        BSc, Hc, EIc, EIc, Hc, Hc, nullptr, 0, nullptr, 0);
}